// round 8
// baseline (speedup 1.0000x reference)
#include <cuda_runtime.h>
#include <cuda_bf16.h>
#include <math.h>

// PLIF neuron scan: x[B,T,C] -> spikes[B,T,C]
//   v = v*sigmoid(decay_param[c]) + x[b,t,c]; s = (v > 0.5); v -= 0.5*s
// B=128, T=256, C=2048.
//
// R8: read/write turnaround batching on top of R7's geometry (grid=128,
// block=512, one row per block, sequential 2MB streams, lowest bench
// overhead). Loop restructured into batches of 8 timesteps:
//   8 back-to-back LDG.128 (refill) -> 8 compute steps -> 8 back-to-back
//   STG.128 (drain), so each warp presents 4KB read bursts alternating
//   with 4KB write bursts instead of per-timestep LD/ST interleave.
// Evidence basis: R1/R4/R5/R6/R7 all converge at DRAM 77+-1% across every
// SM-side config -> only remaining untested mechanism is DRAM-side
// read/write turnaround frequency.

#define T_STEPS 256
#define C_CH    2048
#define GROUPS  (C_CH / 4)   // 512 float4 groups = one full row per block
#define BT      8            // timestep batch (load burst = store burst = 8)

static_assert(T_STEPS % BT == 0, "T must be a multiple of batch");

__global__ __launch_bounds__(512, 1)   // 128-reg cap
void plif_scan_kernel(const float* __restrict__ x,
                      const float* __restrict__ decay_param,
                      float* __restrict__ out)
{
    const int g = threadIdx.x;           // float4 group within C (0..511)
    const int b = blockIdx.x;            // batch row (0..127)

    // Per-channel decay = sigmoid(decay_param). Computed once; IEEE expf to
    // avoid compounded drift over 256 recurrence steps.
    const float4 dp = reinterpret_cast<const float4*>(decay_param)[g];
    const float d0 = 1.0f / (1.0f + expf(-dp.x));
    const float d1 = 1.0f / (1.0f + expf(-dp.y));
    const float d2 = 1.0f / (1.0f + expf(-dp.z));
    const float d3 = 1.0f / (1.0f + expf(-dp.w));

    const float4* xp = reinterpret_cast<const float4*>(x)
                     + (size_t)b * (T_STEPS * GROUPS) + g;
    float4*       op = reinterpret_cast<float4*>(out)
                     + (size_t)b * (T_STEPS * GROUPS) + g;

    float v0 = 0.0f, v1 = 0.0f, v2 = 0.0f, v3 = 0.0f;

    // Prime: first 8-load burst.
    float4 buf[BT];
#pragma unroll
    for (int j = 0; j < BT; j++)
        buf[j] = __ldcs(xp + j * GROUPS);

    for (int tb = 0; tb < T_STEPS; tb += BT) {
        // Consume current batch into 'cur'; immediately refill 'buf' with
        // the NEXT 8-load burst so the loads overlap this batch's compute.
        float4 cur[BT];
#pragma unroll
        for (int j = 0; j < BT; j++)
            cur[j] = buf[j];

        if (tb + BT < T_STEPS) {
#pragma unroll
            for (int j = 0; j < BT; j++)
                buf[j] = __ldcs(xp + (tb + BT + j) * GROUPS);
        }

        // Compute 8 recurrence steps into a register spike buffer.
        float4 sbuf[BT];
#pragma unroll
        for (int j = 0; j < BT; j++) {
            v0 = fmaf(v0, d0, cur[j].x);
            v1 = fmaf(v1, d1, cur[j].y);
            v2 = fmaf(v2, d2, cur[j].z);
            v3 = fmaf(v3, d3, cur[j].w);
            const float s0 = (v0 > 0.5f) ? 1.0f : 0.0f;
            const float s1 = (v1 > 0.5f) ? 1.0f : 0.0f;
            const float s2 = (v2 > 0.5f) ? 1.0f : 0.0f;
            const float s3 = (v3 > 0.5f) ? 1.0f : 0.0f;
            v0 = fmaf(s0, -0.5f, v0);
            v1 = fmaf(s1, -0.5f, v1);
            v2 = fmaf(s2, -0.5f, v2);
            v3 = fmaf(s3, -0.5f, v3);
            sbuf[j] = make_float4(s0, s1, s2, s3);
        }

        // Drain: 8 back-to-back STG.128 (write burst).
#pragma unroll
        for (int j = 0; j < BT; j++)
            __stcs(op + (tb + j) * GROUPS, sbuf[j]);
    }
}

extern "C" void kernel_launch(void* const* d_in, const int* in_sizes, int n_in,
                              void* d_out, int out_size)
{
    const float* x  = (const float*)d_in[0];        // [128, 256, 2048]
    const float* dp = (const float*)d_in[1];        // [2048]
    float*       o  = (float*)d_out;                // [128, 256, 2048]

    plif_scan_kernel<<<128, 512>>>(x, dp, o);       // one block per batch row
}

// round 9
// speedup vs baseline: 1.0164x; 1.0164x over previous
#include <cuda_runtime.h>
#include <cuda_bf16.h>
#include <math.h>

// PLIF neuron scan: x[B,T,C] -> spikes[B,T,C]
//   v = v*sigmoid(decay_param[c]) + x[b,t,c]; s = (v > 0.5); v -= 0.5*s
// B=128, T=256, C=2048.
//
// R9 = R7 confirmation run (best bench 90.9us, kernel 78.8us, DRAM 77.9%).
// Search summary: six configs (occ 20-40%, PF 8-16, block 128-512,
// strided vs sequential block streams, interleaved vs burst R/W) all
// converge at DRAM 77-78.5% / ~6.2 TB/s -> that is the achievable mixed
// read+write HBM efficiency for this workload; R7's mapping (one block
// per batch row, sequential 2MB read & write streams, single balanced
// wave) is the empirical optimum.

#define T_STEPS 256
#define C_CH    2048
#define GROUPS  (C_CH / 4)   // 512 float4 groups = one full row per block
#define PF      8            // prefetch depth (proven optimal: 8 > 16, 8 > burst)

static_assert((T_STEPS - PF) % PF == 0, "steady loop must be multiple of PF");

__global__ __launch_bounds__(512, 1)   // 128-reg cap; body ~78 regs, no spill
void plif_scan_kernel(const float* __restrict__ x,
                      const float* __restrict__ decay_param,
                      float* __restrict__ out)
{
    const int g = threadIdx.x;           // float4 group within C (0..511)
    const int b = blockIdx.x;            // batch row (0..127)

    // Per-channel decay = sigmoid(decay_param). Computed once; IEEE expf to
    // avoid compounded drift over 256 recurrence steps.
    const float4 dp = reinterpret_cast<const float4*>(decay_param)[g];
    const float d0 = 1.0f / (1.0f + expf(-dp.x));
    const float d1 = 1.0f / (1.0f + expf(-dp.y));
    const float d2 = 1.0f / (1.0f + expf(-dp.z));
    const float d3 = 1.0f / (1.0f + expf(-dp.w));

    const float4* xp = reinterpret_cast<const float4*>(x)
                     + (size_t)b * (T_STEPS * GROUPS) + g;
    float4*       op = reinterpret_cast<float4*>(out)
                     + (size_t)b * (T_STEPS * GROUPS) + g;

    float v0 = 0.0f, v1 = 0.0f, v2 = 0.0f, v3 = 0.0f;

    // Prime the ring: PF independent in-flight LDG.128 per thread.
    float4 buf[PF];
#pragma unroll
    for (int i = 0; i < PF; i++)
        buf[i] = __ldcs(xp + i * GROUPS);

#define PLIF_STEP(CUR)                                                  \
    do {                                                                \
        v0 = fmaf(v0, d0, (CUR).x);                                     \
        v1 = fmaf(v1, d1, (CUR).y);                                     \
        v2 = fmaf(v2, d2, (CUR).z);                                     \
        v3 = fmaf(v3, d3, (CUR).w);                                     \
        const float s0 = (v0 > 0.5f) ? 1.0f : 0.0f;                     \
        const float s1 = (v1 > 0.5f) ? 1.0f : 0.0f;                     \
        const float s2 = (v2 > 0.5f) ? 1.0f : 0.0f;                     \
        const float s3 = (v3 > 0.5f) ? 1.0f : 0.0f;                     \
        v0 = fmaf(s0, -0.5f, v0);                                       \
        v1 = fmaf(s1, -0.5f, v1);                                       \
        v2 = fmaf(s2, -0.5f, v2);                                       \
        v3 = fmaf(s3, -0.5f, v3);                                       \
        __stcs(op + t * GROUPS, make_float4(s0, s1, s2, s3));           \
    } while (0)

    // Steady state: 248 iters = 31 * 8; unroll-8 keeps the ring index a
    // compile-time constant (pure registers).
#pragma unroll 8
    for (int t = 0; t < T_STEPS - PF; t++) {
        const float4 cur = buf[t & (PF - 1)];
        buf[t & (PF - 1)] = __ldcs(xp + (t + PF) * GROUPS);
        PLIF_STEP(cur);
    }

    // Epilogue: drain the ring, no further loads.
#pragma unroll
    for (int t = T_STEPS - PF; t < T_STEPS; t++) {
        const float4 cur = buf[t & (PF - 1)];
        PLIF_STEP(cur);
    }
#undef PLIF_STEP
}

extern "C" void kernel_launch(void* const* d_in, const int* in_sizes, int n_in,
                              void* d_out, int out_size)
{
    const float* x  = (const float*)d_in[0];        // [128, 256, 2048]
    const float* dp = (const float*)d_in[1];        // [2048]
    float*       o  = (float*)d_out;                // [128, 256, 2048]

    plif_scan_kernel<<<128, 512>>>(x, dp, o);       // one block per batch row
}

// round 10
// speedup vs baseline: 1.0352x; 1.0185x over previous
#include <cuda_runtime.h>
#include <cuda_bf16.h>
#include <math.h>

// PLIF neuron scan: x[B,T,C] -> spikes[B,T,C]
//   v = v*sigmoid(decay_param[c]) + x[b,t,c]; s = (v > 0.5); v -= 0.5*s
// B=128, T=256, C=2048.
//
// R10 = R9 (confirmed best: bench 89.8us, kernel 78.0us, DRAM 78.9%) with
// ONE isolated change: stores __stcs -> __stwt (write-through). Output has
// zero reuse; write-through skips the L2 write-allocate/dirty-writeback
// path, full 128B sectors per warp so no partial-line penalty. Last
// untested memory-path knob after six falsified SM-side/pattern levers.

#define T_STEPS 256
#define C_CH    2048
#define GROUPS  (C_CH / 4)   // 512 float4 groups = one full row per block
#define PF      8            // prefetch depth (proven optimal: 8 > 16, 8 > burst)

static_assert((T_STEPS - PF) % PF == 0, "steady loop must be multiple of PF");

__global__ __launch_bounds__(512, 1)   // 128-reg cap; body ~78 regs, no spill
void plif_scan_kernel(const float* __restrict__ x,
                      const float* __restrict__ decay_param,
                      float* __restrict__ out)
{
    const int g = threadIdx.x;           // float4 group within C (0..511)
    const int b = blockIdx.x;            // batch row (0..127)

    // Per-channel decay = sigmoid(decay_param). Computed once; IEEE expf to
    // avoid compounded drift over 256 recurrence steps.
    const float4 dp = reinterpret_cast<const float4*>(decay_param)[g];
    const float d0 = 1.0f / (1.0f + expf(-dp.x));
    const float d1 = 1.0f / (1.0f + expf(-dp.y));
    const float d2 = 1.0f / (1.0f + expf(-dp.z));
    const float d3 = 1.0f / (1.0f + expf(-dp.w));

    const float4* xp = reinterpret_cast<const float4*>(x)
                     + (size_t)b * (T_STEPS * GROUPS) + g;
    float4*       op = reinterpret_cast<float4*>(out)
                     + (size_t)b * (T_STEPS * GROUPS) + g;

    float v0 = 0.0f, v1 = 0.0f, v2 = 0.0f, v3 = 0.0f;

    // Prime the ring: PF independent in-flight LDG.128 per thread.
    float4 buf[PF];
#pragma unroll
    for (int i = 0; i < PF; i++)
        buf[i] = __ldcs(xp + i * GROUPS);

#define PLIF_STEP(CUR)                                                  \
    do {                                                                \
        v0 = fmaf(v0, d0, (CUR).x);                                     \
        v1 = fmaf(v1, d1, (CUR).y);                                     \
        v2 = fmaf(v2, d2, (CUR).z);                                     \
        v3 = fmaf(v3, d3, (CUR).w);                                     \
        const float s0 = (v0 > 0.5f) ? 1.0f : 0.0f;                     \
        const float s1 = (v1 > 0.5f) ? 1.0f : 0.0f;                     \
        const float s2 = (v2 > 0.5f) ? 1.0f : 0.0f;                     \
        const float s3 = (v3 > 0.5f) ? 1.0f : 0.0f;                     \
        v0 = fmaf(s0, -0.5f, v0);                                       \
        v1 = fmaf(s1, -0.5f, v1);                                       \
        v2 = fmaf(s2, -0.5f, v2);                                       \
        v3 = fmaf(s3, -0.5f, v3);                                       \
        __stwt(op + t * GROUPS, make_float4(s0, s1, s2, s3));           \
    } while (0)

    // Steady state: 248 iters = 31 * 8; unroll-8 keeps the ring index a
    // compile-time constant (pure registers).
#pragma unroll 8
    for (int t = 0; t < T_STEPS - PF; t++) {
        const float4 cur = buf[t & (PF - 1)];
        buf[t & (PF - 1)] = __ldcs(xp + (t + PF) * GROUPS);
        PLIF_STEP(cur);
    }

    // Epilogue: drain the ring, no further loads.
#pragma unroll
    for (int t = T_STEPS - PF; t < T_STEPS; t++) {
        const float4 cur = buf[t & (PF - 1)];
        PLIF_STEP(cur);
    }
#undef PLIF_STEP
}

extern "C" void kernel_launch(void* const* d_in, const int* in_sizes, int n_in,
                              void* d_out, int out_size)
{
    const float* x  = (const float*)d_in[0];        // [128, 256, 2048]
    const float* dp = (const float*)d_in[1];        // [2048]
    float*       o  = (float*)d_out;                // [128, 256, 2048]

    plif_scan_kernel<<<128, 512>>>(x, dp, o);       // one block per batch row
}